// round 1
// baseline (speedup 1.0000x reference)
#include <cuda_runtime.h>
#include <cuda_bf16.h>
#include <mma.h>

using namespace nvcuda;

#define NN 8192
#define HH 64

// Scratch (no allocation allowed)
__device__ float g_h[NN * HH];
__device__ float g_agg[NN * HH];
__device__ __nv_bfloat16 g_qb[NN * HH];
__device__ __nv_bfloat16 g_kb[NN * HH];
__device__ __nv_bfloat16 g_mb[NN * HH];
__device__ float g_scal[2];   // [0] = gate_factor/8, [1] = stateful_bias[0]*(1-tc0)

// ---------------------------------------------------------------------------
// Fast exp on the FMA pipe (avoids MUFU bottleneck: 67M exps)
// exp(x) = 2^(x*log2e); degree-4 poly for 2^f on [-0.5,0.5], rel err ~4e-5.
// x = -1e9 clamps to 2^-126 * 1 ~ 1.2e-38 -> effectively 0 (matches reference).
__device__ __forceinline__ float fexp(float x) {
    float t = x * 1.4426950408889634f;
    t = fmaxf(t, -126.0f);
    float r = rintf(t);
    float f = t - r;
    float p = fmaf(f, 0.0096181291f, 0.0555041087f);
    p = fmaf(f, p, 0.2402265070f);
    p = fmaf(f, p, 0.6931471806f);
    p = fmaf(f, p, 1.0f);
    return __int_as_float(((int)r + 127) << 23) * p;
}

// ---------------------------------------------------------------------------
// K0: gate_factor = mean(sigmoid(tc @ wg + bg)); sb coefficient.
__global__ void k_scalars(const float* __restrict__ tc, const float* __restrict__ wg,
                          const float* __restrict__ bg, const float* __restrict__ sb) {
    int t = threadIdx.x;  // 64 threads
    float v = fmaf(tc[0], wg[t], fmaf(tc[1], wg[64 + t], bg[t]));
    v = 1.0f / (1.0f + __expf(-v));
#pragma unroll
    for (int o = 16; o >= 1; o >>= 1) v += __shfl_xor_sync(0xffffffffu, v, o);
    __shared__ float red[2];
    if ((t & 31) == 0) red[t >> 5] = v;
    __syncthreads();
    if (t == 0) {
        float g = (red[0] + red[1]) * (1.0f / 64.0f);
        g_scal[0] = g * 0.125f;              // gate / sqrt(H)
        g_scal[1] = sb[0] * (1.0f - tc[0]);  // stateful bias coefficient
    }
}

// ---------------------------------------------------------------------------
// K1 helpers: 64x64 GEMM stage, 256 threads, 4x4 micro-tiles.
__device__ __forceinline__ void loadW(float* sW, const float* __restrict__ w, int tid) {
    float4* d = (float4*)sW;
    const float4* s = (const float4*)w;
#pragma unroll
    for (int k2 = 0; k2 < 4; k2++) d[tid + k2 * 256] = s[tid + k2 * 256];
}

__device__ __forceinline__ void gemm64(const float* __restrict__ sIn, const float* __restrict__ sW,
                                       const float* __restrict__ bias, int r0, int c0,
                                       float acc[4][4]) {
    float4 bb = *(const float4*)&bias[c0];
#pragma unroll
    for (int i = 0; i < 4; i++) {
        acc[i][0] = bb.x; acc[i][1] = bb.y; acc[i][2] = bb.z; acc[i][3] = bb.w;
    }
#pragma unroll 8
    for (int j = 0; j < 64; j++) {
        float4 wv = *(const float4*)&sW[j * 64 + c0];
#pragma unroll
        for (int i = 0; i < 4; i++) {
            float av = sIn[(r0 + i) * 64 + j];
            acc[i][0] = fmaf(av, wv.x, acc[i][0]);
            acc[i][1] = fmaf(av, wv.y, acc[i][1]);
            acc[i][2] = fmaf(av, wv.z, acc[i][2]);
            acc[i][3] = fmaf(av, wv.w, acc[i][3]);
        }
    }
}

__device__ __forceinline__ void store_bf16_row4(__nv_bfloat16* dst, const float* a, float s) {
    __nv_bfloat162 v01, v23;
    v01.x = __float2bfloat16(a[0] * s); v01.y = __float2bfloat16(a[1] * s);
    v23.x = __float2bfloat16(a[2] * s); v23.y = __float2bfloat16(a[3] * s);
    ((__nv_bfloat162*)dst)[0] = v01;
    ((__nv_bfloat162*)dst)[1] = v23;
}

// K1: h = relu(x@w1+b1)@w2+b2 ; q=(h@wq+bq)*gate/8 ; k=h@wk+bk ; msg=h@wm+bm
__global__ __launch_bounds__(256) void k_prep(
    const float* __restrict__ nf, const float* __restrict__ tc,
    const float* __restrict__ w1, const float* __restrict__ b1,
    const float* __restrict__ w2, const float* __restrict__ b2,
    const float* __restrict__ wq, const float* __restrict__ bq,
    const float* __restrict__ wk, const float* __restrict__ bk,
    const float* __restrict__ wm, const float* __restrict__ bm) {
    __shared__ float sA[64 * 64];
    __shared__ float sW[64 * 64];
    const int tid = threadIdx.x;
    const int r0 = (tid >> 4) << 2;
    const int c0 = (tid & 15) << 2;
    const int q0 = blockIdx.x * 64;
    const float tc0 = tc[0], tc1 = tc[1];

    // Stage 0: a = relu(x @ w1 + b1)
    float x0[4], x1[4], x2[4];
#pragma unroll
    for (int i = 0; i < 4; i++) {
        int row = q0 + r0 + i;
        x0[i] = nf[row * 3 + 0]; x1[i] = nf[row * 3 + 1]; x2[i] = nf[row * 3 + 2];
    }
#pragma unroll
    for (int c = 0; c < 4; c++) {
        int col = c0 + c;
        float wv0 = w1[col], wv1 = w1[64 + col], wv2 = w1[128 + col];
        float bb = fmaf(tc0, w1[192 + col], fmaf(tc1, w1[256 + col], b1[col]));
#pragma unroll
        for (int i = 0; i < 4; i++) {
            float a = fmaf(x0[i], wv0, fmaf(x1[i], wv1, fmaf(x2[i], wv2, bb)));
            sA[(r0 + i) * 64 + col] = fmaxf(a, 0.0f);
        }
    }
    __syncthreads();

    // Stage 1: h = a @ w2 + b2
    loadW(sW, w2, tid);
    __syncthreads();
    float acc[4][4];
    gemm64(sA, sW, b2, r0, c0, acc);
    __syncthreads();
#pragma unroll
    for (int i = 0; i < 4; i++) {
        float4 hv = make_float4(acc[i][0], acc[i][1], acc[i][2], acc[i][3]);
        *(float4*)&sA[(r0 + i) * 64 + c0] = hv;                     // sA now holds h
        *(float4*)&g_h[(q0 + r0 + i) * 64 + c0] = hv;
    }
    __syncthreads();

    // Stage 2: q (pre-scaled by gate/8, bf16)
    loadW(sW, wq, tid);
    __syncthreads();
    gemm64(sA, sW, bq, r0, c0, acc);
    {
        float qs = g_scal[0];
#pragma unroll
        for (int i = 0; i < 4; i++)
            store_bf16_row4(&g_qb[(q0 + r0 + i) * 64 + c0], acc[i], qs);
    }
    __syncthreads();

    // Stage 3: k (bf16)
    loadW(sW, wk, tid);
    __syncthreads();
    gemm64(sA, sW, bk, r0, c0, acc);
#pragma unroll
    for (int i = 0; i < 4; i++)
        store_bf16_row4(&g_kb[(q0 + r0 + i) * 64 + c0], acc[i], 1.0f);
    __syncthreads();

    // Stage 4: messages (bf16)
    loadW(sW, wm, tid);
    __syncthreads();
    gemm64(sA, sW, bm, r0, c0, acc);
#pragma unroll
    for (int i = 0; i < 4; i++)
        store_bf16_row4(&g_mb[(q0 + r0 + i) * 64 + c0], acc[i], 1.0f);
}

// ---------------------------------------------------------------------------
// K2: fused flash-attention. BM=BN=64, 8 warps, wmma bf16 16x16x16.
// scores bounded by ~1 => no running max needed; exp(-1e9) underflows to ~0.
__global__ __launch_bounds__(256) void k_attn(const float* __restrict__ adj,
                                              const float* __restrict__ nf) {
    __shared__ __nv_bfloat16 sQ[64 * 64];   // 8 KB
    __shared__ __nv_bfloat16 sK[64 * 64];   // 8 KB
    __shared__ __nv_bfloat16 sV[64 * 64];   // 8 KB
    __shared__ float sS[64 * 64];           // 16 KB (P bf16 aliases this)
    __shared__ float sDen[64];
    __shared__ float sStQ[64];
    __shared__ float sStK[64];
    __nv_bfloat16* sP = (__nv_bfloat16*)sS;

    const int tid = threadIdx.x;
    const int warp = tid >> 5;
    const int wm_ = warp >> 1;   // 0..3 : 16-row group
    const int wn_ = warp & 1;    // 0..1 : 32-col group
    const int rgrp = tid >> 4;   // 0..15
    const int fidx = tid & 15;   // float4 index within row
    const int q0 = blockIdx.x * 64;

    // Stage Q (8 KB contiguous) + stateful(q)
    {
        const uint4* s = (const uint4*)(g_qb + q0 * 64);
        uint4* d = (uint4*)sQ;
        d[tid] = s[tid]; d[tid + 256] = s[tid + 256];
    }
    if (tid < 64) sStQ[tid] = nf[(q0 + tid) * 3 + 2];
    const float sbc = g_scal[1];

    float den0 = 0.f, den1 = 0.f, den2 = 0.f, den3 = 0.f;
    wmma::fragment<wmma::accumulator, 16, 16, 16, float> o0, o1;
    wmma::fill_fragment(o0, 0.0f);
    wmma::fill_fragment(o1, 0.0f);

    uint4 kr0, kr1, vr0, vr1;
    float4 a0, a1, a2, a3;
    float stk = 0.0f;

    // Prefetch tile 0
    {
        const uint4* ks = (const uint4*)g_kb;
        const uint4* vs = (const uint4*)g_mb;
        kr0 = ks[tid]; kr1 = ks[tid + 256];
        vr0 = vs[tid]; vr1 = vs[tid + 256];
        a0 = *(const float4*)&adj[(q0 + rgrp)      * NN + fidx * 4];
        a1 = *(const float4*)&adj[(q0 + rgrp + 16) * NN + fidx * 4];
        a2 = *(const float4*)&adj[(q0 + rgrp + 32) * NN + fidx * 4];
        a3 = *(const float4*)&adj[(q0 + rgrp + 48) * NN + fidx * 4];
        if (tid < 64) stk = nf[tid * 3 + 2];
    }

    for (int t = 0; t < 128; t++) {
        __syncthreads();  // previous tile's P@V done reading sK/sV/sP
        {   // stage K/V tile + stateful(k)
            uint4* kd = (uint4*)sK; kd[tid] = kr0; kd[tid + 256] = kr1;
            uint4* vd = (uint4*)sV; vd[tid] = vr0; vd[tid + 256] = vr1;
            if (tid < 64) sStK[tid] = stk;
        }
        __syncthreads();

        // S = Qs @ K^T  (fp32 accumulate)
        {
            wmma::fragment<wmma::accumulator, 16, 16, 16, float> s0, s1;
            wmma::fill_fragment(s0, 0.0f);
            wmma::fill_fragment(s1, 0.0f);
#pragma unroll
            for (int kk = 0; kk < 4; kk++) {
                wmma::fragment<wmma::matrix_a, 16, 16, 16, __nv_bfloat16, wmma::row_major> fa;
                wmma::load_matrix_sync(fa, sQ + wm_ * 16 * 64 + kk * 16, 64);
                wmma::fragment<wmma::matrix_b, 16, 16, 16, __nv_bfloat16, wmma::col_major> fb0, fb1;
                wmma::load_matrix_sync(fb0, sK + (wn_ * 32)      * 64 + kk * 16, 64);
                wmma::load_matrix_sync(fb1, sK + (wn_ * 32 + 16) * 64 + kk * 16, 64);
                wmma::mma_sync(s0, fa, fb0, s0);
                wmma::mma_sync(s1, fa, fb1, s1);
            }
            wmma::store_matrix_sync(sS + wm_ * 16 * 64 + wn_ * 32,      s0, 64, wmma::mem_row_major);
            wmma::store_matrix_sync(sS + wm_ * 16 * 64 + wn_ * 32 + 16, s1, 64, wmma::mem_row_major);
        }
        __syncthreads();

        // Pointwise: P = exp(S + topo + sb), row-sum into den
        float pv[4][4];
        float rs[4];
        {
            float stqv[4] = {sStQ[rgrp], sStQ[rgrp + 16], sStQ[rgrp + 32], sStQ[rgrp + 48]};
            float stkv[4];
#pragma unroll
            for (int c = 0; c < 4; c++) stkv[c] = sStK[fidx * 4 + c];
            float4 av[4] = {a0, a1, a2, a3};
#pragma unroll
            for (int i = 0; i < 4; i++) {
                int row = rgrp + 16 * i;
                float4 sv = *(const float4*)&sS[row * 64 + fidx * 4];
                const float* ap = &av[i].x;
                const float* sp = &sv.x;
                float r = 0.0f;
#pragma unroll
                for (int c = 0; c < 4; c++) {
                    float a = ap[c];
                    float topo = (a == 0.0f) ? -1e9f : a;
                    float s = sp[c] + topo + sbc * stqv[i] * stkv[c];
                    float p = fexp(s);
                    pv[i][c] = p;
                    r += p;
                }
                rs[i] = r;
            }
        }
#pragma unroll
        for (int i = 0; i < 4; i++) {
            float r = rs[i];
            r += __shfl_xor_sync(0xffffffffu, r, 1);
            r += __shfl_xor_sync(0xffffffffu, r, 2);
            r += __shfl_xor_sync(0xffffffffu, r, 4);
            r += __shfl_xor_sync(0xffffffffu, r, 8);
            rs[i] = r;
        }
        if (fidx == 0) { den0 += rs[0]; den1 += rs[1]; den2 += rs[2]; den3 += rs[3]; }

        __syncthreads();  // everyone done reading sS before overwriting with P (aliased)
#pragma unroll
        for (int i = 0; i < 4; i++) {
            int row = rgrp + 16 * i;
            __nv_bfloat162 v01, v23;
            v01.x = __float2bfloat16(pv[i][0]); v01.y = __float2bfloat16(pv[i][1]);
            v23.x = __float2bfloat16(pv[i][2]); v23.y = __float2bfloat16(pv[i][3]);
            __nv_bfloat162* pd = (__nv_bfloat162*)&sP[row * 64 + fidx * 4];
            pd[0] = v01; pd[1] = v23;
        }

        // Prefetch next tile (overlaps with P@V + next S GEMM)
        if (t + 1 < 128) {
            int j0 = (t + 1) * 64;
            const uint4* ks = (const uint4*)(g_kb + j0 * 64);
            const uint4* vs = (const uint4*)(g_mb + j0 * 64);
            kr0 = ks[tid]; kr1 = ks[tid + 256];
            vr0 = vs[tid]; vr1 = vs[tid + 256];
            a0 = *(const float4*)&adj[(q0 + rgrp)      * NN + j0 + fidx * 4];
            a1 = *(const float4*)&adj[(q0 + rgrp + 16) * NN + j0 + fidx * 4];
            a2 = *(const float4*)&adj[(q0 + rgrp + 32) * NN + j0 + fidx * 4];
            a3 = *(const float4*)&adj[(q0 + rgrp + 48) * NN + j0 + fidx * 4];
            if (tid < 64) stk = nf[(j0 + tid) * 3 + 2];
        }
        __syncthreads();

        // O += P @ V
#pragma unroll
        for (int kk = 0; kk < 4; kk++) {
            wmma::fragment<wmma::matrix_a, 16, 16, 16, __nv_bfloat16, wmma::row_major> fp;
            wmma::load_matrix_sync(fp, sP + wm_ * 16 * 64 + kk * 16, 64);
            wmma::fragment<wmma::matrix_b, 16, 16, 16, __nv_bfloat16, wmma::row_major> fv0, fv1;
            wmma::load_matrix_sync(fv0, sV + kk * 16 * 64 + wn_ * 32, 64);
            wmma::load_matrix_sync(fv1, sV + kk * 16 * 64 + wn_ * 32 + 16, 64);
            wmma::mma_sync(o0, fp, fv0, o0);
            wmma::mma_sync(o1, fp, fv1, o1);
        }
    }

    if (fidx == 0) {
        sDen[rgrp] = den0; sDen[rgrp + 16] = den1;
        sDen[rgrp + 32] = den2; sDen[rgrp + 48] = den3;
    }
    __syncthreads();  // P@V reads of sP done; den complete
    wmma::store_matrix_sync(sS + wm_ * 16 * 64 + wn_ * 32,      o0, 64, wmma::mem_row_major);
    wmma::store_matrix_sync(sS + wm_ * 16 * 64 + wn_ * 32 + 16, o1, 64, wmma::mem_row_major);
    if (tid < 64) sDen[tid] = 1.0f / sDen[tid];
    __syncthreads();
#pragma unroll
    for (int k2 = 0; k2 < 16; k2++) {
        int idx = tid + k2 * 256;
        int row = idx >> 6;
        g_agg[(q0 + row) * 64 + (idx & 63)] = sS[idx] * sDen[row];
    }
}

// ---------------------------------------------------------------------------
// K3: z = h + agg ; LayerNorm ; concat sa ; relu(ai@wa1+ba1)@wa2+ba2
__global__ __launch_bounds__(256) void k_epi(
    const float* __restrict__ sa, const float* __restrict__ lng, const float* __restrict__ lnb,
    const float* __restrict__ wa1, const float* __restrict__ ba1,
    const float* __restrict__ wa2, const float* __restrict__ ba2,
    float* __restrict__ out) {
    __shared__ float sAi[8][68];
    const int warp = threadIdx.x >> 5;
    const int lane = threadIdx.x & 31;
    const int row = blockIdx.x * 8 + warp;
    const int c0 = lane, c1 = lane + 32;

    float z0 = g_h[row * 64 + c0] + g_agg[row * 64 + c0];
    float z1 = g_h[row * 64 + c1] + g_agg[row * 64 + c1];
    float s = z0 + z1;
#pragma unroll
    for (int o = 16; o >= 1; o >>= 1) s += __shfl_xor_sync(0xffffffffu, s, o);
    float mu = s * (1.0f / 64.0f);
    float d0 = z0 - mu, d1 = z1 - mu;
    float v = d0 * d0 + d1 * d1;
#pragma unroll
    for (int o = 16; o >= 1; o >>= 1) v += __shfl_xor_sync(0xffffffffu, v, o);
    float inv = rsqrtf(v * (1.0f / 64.0f) + 1e-5f);
    sAi[warp][c0] = fmaf(d0 * inv, lng[c0], lnb[c0]);
    sAi[warp][c1] = fmaf(d1 * inv, lng[c1], lnb[c1]);
    if (lane < 2) sAi[warp][64 + lane] = sa[row * 2 + lane];
    __syncwarp();

    float acc0 = ba1[c0], acc1 = ba1[c1];
#pragma unroll 11
    for (int i = 0; i < 66; i++) {
        float av = sAi[warp][i];
        acc0 = fmaf(av, wa1[i * 64 + c0], acc0);
        acc1 = fmaf(av, wa1[i * 64 + c1], acc1);
    }
    acc0 = fmaxf(acc0, 0.0f);
    acc1 = fmaxf(acc1, 0.0f);
    float q0v = fmaf(acc0, wa2[c0 * 3 + 0], acc1 * wa2[c1 * 3 + 0]);
    float q1v = fmaf(acc0, wa2[c0 * 3 + 1], acc1 * wa2[c1 * 3 + 1]);
    float q2v = fmaf(acc0, wa2[c0 * 3 + 2], acc1 * wa2[c1 * 3 + 2]);
#pragma unroll
    for (int o = 16; o >= 1; o >>= 1) {
        q0v += __shfl_xor_sync(0xffffffffu, q0v, o);
        q1v += __shfl_xor_sync(0xffffffffu, q1v, o);
        q2v += __shfl_xor_sync(0xffffffffu, q2v, o);
    }
    if (lane == 0) {
        out[row * 3 + 0] = q0v + ba2[0];
        out[row * 3 + 1] = q1v + ba2[1];
        out[row * 3 + 2] = q2v + ba2[2];
    }
}

// ---------------------------------------------------------------------------
extern "C" void kernel_launch(void* const* d_in, const int* in_sizes, int n_in,
                              void* d_out, int out_size) {
    const float* nf    = (const float*)d_in[0];
    const float* adj   = (const float*)d_in[1];
    const float* tc    = (const float*)d_in[2];
    const float* sa    = (const float*)d_in[3];
    const float* w1    = (const float*)d_in[4];
    const float* b1    = (const float*)d_in[5];
    const float* w2    = (const float*)d_in[6];
    const float* b2    = (const float*)d_in[7];
    const float* wq    = (const float*)d_in[8];
    const float* bq    = (const float*)d_in[9];
    const float* wk    = (const float*)d_in[10];
    const float* bk    = (const float*)d_in[11];
    const float* wg    = (const float*)d_in[12];
    const float* bg    = (const float*)d_in[13];
    const float* sbias = (const float*)d_in[14];
    const float* wm    = (const float*)d_in[15];
    const float* bm    = (const float*)d_in[16];
    const float* lng   = (const float*)d_in[17];
    const float* lnb   = (const float*)d_in[18];
    const float* wa1   = (const float*)d_in[19];
    const float* ba1   = (const float*)d_in[20];
    const float* wa2   = (const float*)d_in[21];
    const float* ba2   = (const float*)d_in[22];
    float* out = (float*)d_out;

    k_scalars<<<1, 64>>>(tc, wg, bg, sbias);
    k_prep<<<128, 256>>>(nf, tc, w1, b1, w2, b2, wq, bq, wk, bk, wm, bm);
    k_attn<<<128, 256>>>(adj, nf);
    k_epi<<<1024, 256>>>(sa, lng, lnb, wa1, ba1, wa2, ba2, out);
}

// round 2
// speedup vs baseline: 2.8735x; 2.8735x over previous
#include <cuda_runtime.h>
#include <cuda_bf16.h>
#include <mma.h>

using namespace nvcuda;

#define NN 8192
#define HH 64
#define LQ 72            // padded leading dim (elements) for all smem tiles

// Scratch (no allocation allowed)
__device__ float g_h[NN * HH];
__device__ float g_aggp[2][NN * HH];   // split-KV partial numerators
__device__ float g_denp[2][NN];        // split-KV partial denominators
__device__ __nv_bfloat16 g_qb[NN * HH];
__device__ __nv_bfloat16 g_kb[NN * HH];
__device__ __nv_bfloat16 g_mb[NN * HH];
__device__ float g_scal[2];   // [0] = gate_factor/8, [1] = stateful_bias[0]*(1-tc0)

// ---------------------------------------------------------------------------
// Fast exp on the FMA pipe. exp(-1e9) -> ~1.2e-38 (effectively 0, matches ref).
__device__ __forceinline__ float fexp(float x) {
    float t = x * 1.4426950408889634f;
    t = fmaxf(t, -126.0f);
    float r = rintf(t);
    float f = t - r;
    float p = fmaf(f, 0.0096181291f, 0.0555041087f);
    p = fmaf(f, p, 0.2402265070f);
    p = fmaf(f, p, 0.6931471806f);
    p = fmaf(f, p, 1.0f);
    return __int_as_float(((int)r + 127) << 23) * p;
}

// ---------------------------------------------------------------------------
__global__ void k_scalars(const float* __restrict__ tc, const float* __restrict__ wg,
                          const float* __restrict__ bg, const float* __restrict__ sb) {
    int t = threadIdx.x;  // 64 threads
    float v = fmaf(tc[0], wg[t], fmaf(tc[1], wg[64 + t], bg[t]));
    v = 1.0f / (1.0f + __expf(-v));
#pragma unroll
    for (int o = 16; o >= 1; o >>= 1) v += __shfl_xor_sync(0xffffffffu, v, o);
    __shared__ float red[2];
    if ((t & 31) == 0) red[t >> 5] = v;
    __syncthreads();
    if (t == 0) {
        float g = (red[0] + red[1]) * (1.0f / 64.0f);
        g_scal[0] = g * 0.125f;
        g_scal[1] = sb[0] * (1.0f - tc[0]);
    }
}

// ---------------------------------------------------------------------------
__device__ __forceinline__ void loadW(float* sW, const float* __restrict__ w, int tid) {
    float4* d = (float4*)sW;
    const float4* s = (const float4*)w;
#pragma unroll
    for (int k2 = 0; k2 < 4; k2++) d[tid + k2 * 256] = s[tid + k2 * 256];
}

__device__ __forceinline__ void gemm64(const float* __restrict__ sIn, const float* __restrict__ sW,
                                       const float* __restrict__ bias, int r0, int c0,
                                       float acc[4][4]) {
    float4 bb = *(const float4*)&bias[c0];
#pragma unroll
    for (int i = 0; i < 4; i++) {
        acc[i][0] = bb.x; acc[i][1] = bb.y; acc[i][2] = bb.z; acc[i][3] = bb.w;
    }
#pragma unroll 8
    for (int j = 0; j < 64; j++) {
        float4 wv = *(const float4*)&sW[j * 64 + c0];
#pragma unroll
        for (int i = 0; i < 4; i++) {
            float av = sIn[(r0 + i) * 64 + j];
            acc[i][0] = fmaf(av, wv.x, acc[i][0]);
            acc[i][1] = fmaf(av, wv.y, acc[i][1]);
            acc[i][2] = fmaf(av, wv.z, acc[i][2]);
            acc[i][3] = fmaf(av, wv.w, acc[i][3]);
        }
    }
}

__device__ __forceinline__ void store_bf16_row4(__nv_bfloat16* dst, const float* a, float s) {
    __nv_bfloat162 v01, v23;
    v01.x = __float2bfloat16(a[0] * s); v01.y = __float2bfloat16(a[1] * s);
    v23.x = __float2bfloat16(a[2] * s); v23.y = __float2bfloat16(a[3] * s);
    ((__nv_bfloat162*)dst)[0] = v01;
    ((__nv_bfloat162*)dst)[1] = v23;
}

__global__ __launch_bounds__(256) void k_prep(
    const float* __restrict__ nf, const float* __restrict__ tc,
    const float* __restrict__ w1, const float* __restrict__ b1,
    const float* __restrict__ w2, const float* __restrict__ b2,
    const float* __restrict__ wq, const float* __restrict__ bq,
    const float* __restrict__ wk, const float* __restrict__ bk,
    const float* __restrict__ wm, const float* __restrict__ bm) {
    __shared__ float sA[64 * 64];
    __shared__ float sW[64 * 64];
    const int tid = threadIdx.x;
    const int r0 = (tid >> 4) << 2;
    const int c0 = (tid & 15) << 2;
    const int q0 = blockIdx.x * 64;
    const float tc0 = tc[0], tc1 = tc[1];

    float x0[4], x1[4], x2[4];
#pragma unroll
    for (int i = 0; i < 4; i++) {
        int row = q0 + r0 + i;
        x0[i] = nf[row * 3 + 0]; x1[i] = nf[row * 3 + 1]; x2[i] = nf[row * 3 + 2];
    }
#pragma unroll
    for (int c = 0; c < 4; c++) {
        int col = c0 + c;
        float wv0 = w1[col], wv1 = w1[64 + col], wv2 = w1[128 + col];
        float bb = fmaf(tc0, w1[192 + col], fmaf(tc1, w1[256 + col], b1[col]));
#pragma unroll
        for (int i = 0; i < 4; i++) {
            float a = fmaf(x0[i], wv0, fmaf(x1[i], wv1, fmaf(x2[i], wv2, bb)));
            sA[(r0 + i) * 64 + col] = fmaxf(a, 0.0f);
        }
    }
    __syncthreads();

    loadW(sW, w2, tid);
    __syncthreads();
    float acc[4][4];
    gemm64(sA, sW, b2, r0, c0, acc);
    __syncthreads();
#pragma unroll
    for (int i = 0; i < 4; i++) {
        float4 hv = make_float4(acc[i][0], acc[i][1], acc[i][2], acc[i][3]);
        *(float4*)&sA[(r0 + i) * 64 + c0] = hv;
        *(float4*)&g_h[(q0 + r0 + i) * 64 + c0] = hv;
    }
    __syncthreads();

    loadW(sW, wq, tid);
    __syncthreads();
    gemm64(sA, sW, bq, r0, c0, acc);
    {
        float qs = g_scal[0];
#pragma unroll
        for (int i = 0; i < 4; i++)
            store_bf16_row4(&g_qb[(q0 + r0 + i) * 64 + c0], acc[i], qs);
    }
    __syncthreads();

    loadW(sW, wk, tid);
    __syncthreads();
    gemm64(sA, sW, bk, r0, c0, acc);
#pragma unroll
    for (int i = 0; i < 4; i++)
        store_bf16_row4(&g_kb[(q0 + r0 + i) * 64 + c0], acc[i], 1.0f);
    __syncthreads();

    loadW(sW, wm, tid);
    __syncthreads();
    gemm64(sA, sW, bm, r0, c0, acc);
#pragma unroll
    for (int i = 0; i < 4; i++)
        store_bf16_row4(&g_mb[(q0 + r0 + i) * 64 + c0], acc[i], 1.0f);
}

// ---------------------------------------------------------------------------
// K2: fused flash-attention, split-KV x2, padded smem (conflict-free ldmatrix),
// double-buffered K/V, 2 syncs/iter, 2 CTAs/SM.
#define SQ_OFF   0
#define SK_OFF   9216
#define SV_OFF   27648
#define SS_OFF   46080
#define SP_OFF   64512
#define STQ_OFF  73728
#define STK_OFF  73984
#define SMEM_ATTN 74496

__global__ __launch_bounds__(256, 2) void k_attn(const float* __restrict__ adj,
                                                 const float* __restrict__ nf) {
    extern __shared__ __align__(16) char dsm[];
    __nv_bfloat16* sQ = (__nv_bfloat16*)(dsm + SQ_OFF);
    __nv_bfloat16* sK = (__nv_bfloat16*)(dsm + SK_OFF);   // [2][64*LQ]
    __nv_bfloat16* sV = (__nv_bfloat16*)(dsm + SV_OFF);   // [2][64*LQ]
    float*         sS = (float*)(dsm + SS_OFF);           // [64*LQ]
    __nv_bfloat16* sP = (__nv_bfloat16*)(dsm + SP_OFF);   // [64*LQ]
    float*       sStQ = (float*)(dsm + STQ_OFF);
    float*       sStK = (float*)(dsm + STK_OFF);          // [2][64]

    const int tid = threadIdx.x;
    const int warp = tid >> 5;
    const int wm_ = warp >> 1;
    const int wn_ = warp & 1;
    const int rgrp = tid >> 4;
    const int fidx = tid & 15;
    const int qi = blockIdx.x >> 1;
    const int sp = blockIdx.x & 1;
    const int q0 = qi * 64;
    const int kvb = sp * 4096;
    const int d0 = (tid >> 3) * LQ + (tid & 7) * 8;  // staging dst for linear idx=tid
    const int BUF = 64 * LQ;

    // Stage Q (padded)
    {
        const uint4* qs = (const uint4*)(g_qb + q0 * 64);
        uint4 qa = qs[tid], qb = qs[tid + 256];
        *(uint4*)&sQ[d0] = qa;
        *(uint4*)&sQ[d0 + 32 * LQ] = qb;
    }
    if (tid < 64) sStQ[tid] = nf[(q0 + tid) * 3 + 2];
    const float sbc = g_scal[1];

    const uint4* ks = (const uint4*)(g_kb + kvb * 64);
    const uint4* vs = (const uint4*)(g_mb + kvb * 64);

    // Tile 0 -> buf 0
    {
        uint4 ka = ks[tid], kb2 = ks[tid + 256], va = vs[tid], vb = vs[tid + 256];
        *(uint4*)&sK[d0] = ka;            *(uint4*)&sK[d0 + 32 * LQ] = kb2;
        *(uint4*)&sV[d0] = va;            *(uint4*)&sV[d0 + 32 * LQ] = vb;
        if (tid < 64) sStK[tid] = nf[(kvb + tid) * 3 + 2];
    }
    // Prefetch tile 1 (regs)
    uint4 kr0 = ks[512 + tid], kr1 = ks[512 + tid + 256];
    uint4 vr0 = vs[512 + tid], vr1 = vs[512 + tid + 256];
    float stk = (tid < 64) ? nf[(kvb + 64 + tid) * 3 + 2] : 0.0f;
    // Prefetch adj tile 0 (regs)
    float4 a0, a1, a2, a3;
    {
        const float* ap = adj + (size_t)q0 * NN + kvb;
        a0 = *(const float4*)&ap[(size_t)(rgrp)      * NN + fidx * 4];
        a1 = *(const float4*)&ap[(size_t)(rgrp + 16) * NN + fidx * 4];
        a2 = *(const float4*)&ap[(size_t)(rgrp + 32) * NN + fidx * 4];
        a3 = *(const float4*)&ap[(size_t)(rgrp + 48) * NN + fidx * 4];
    }

    float den[4] = {0.f, 0.f, 0.f, 0.f};
    wmma::fragment<wmma::accumulator, 16, 16, 16, float> o0, o1;
    wmma::fill_fragment(o0, 0.0f);
    wmma::fill_fragment(o1, 0.0f);
    __syncthreads();

    for (int t = 0; t < 64; t++) {
        const int b = t & 1;
        const __nv_bfloat16* sKb = sK + b * BUF;
        const __nv_bfloat16* sVb = sV + b * BUF;

        // S = Q @ K^T
        {
            wmma::fragment<wmma::accumulator, 16, 16, 16, float> s0, s1;
            wmma::fill_fragment(s0, 0.0f);
            wmma::fill_fragment(s1, 0.0f);
#pragma unroll
            for (int kk = 0; kk < 4; kk++) {
                wmma::fragment<wmma::matrix_a, 16, 16, 16, __nv_bfloat16, wmma::row_major> fa;
                wmma::load_matrix_sync(fa, sQ + wm_ * 16 * LQ + kk * 16, LQ);
                wmma::fragment<wmma::matrix_b, 16, 16, 16, __nv_bfloat16, wmma::col_major> fb0, fb1;
                wmma::load_matrix_sync(fb0, sKb + (wn_ * 32)      * LQ + kk * 16, LQ);
                wmma::load_matrix_sync(fb1, sKb + (wn_ * 32 + 16) * LQ + kk * 16, LQ);
                wmma::mma_sync(s0, fa, fb0, s0);
                wmma::mma_sync(s1, fa, fb1, s1);
            }
            wmma::store_matrix_sync(sS + wm_ * 16 * LQ + wn_ * 32,      s0, LQ, wmma::mem_row_major);
            wmma::store_matrix_sync(sS + wm_ * 16 * LQ + wn_ * 32 + 16, s1, LQ, wmma::mem_row_major);
        }
        __syncthreads();   // (A)

        // Pointwise: P = exp(S + topo + sb); row-sums
        {
            float stqv[4] = {sStQ[rgrp], sStQ[rgrp + 16], sStQ[rgrp + 32], sStQ[rgrp + 48]};
            float stkv[4];
#pragma unroll
            for (int c = 0; c < 4; c++) stkv[c] = sStK[b * 64 + fidx * 4 + c];
            float4 av[4] = {a0, a1, a2, a3};
#pragma unroll
            for (int i = 0; i < 4; i++) {
                int row = rgrp + 16 * i;
                float4 sv = *(const float4*)&sS[row * LQ + fidx * 4];
                const float* ap2 = &av[i].x;
                const float* sp2 = &sv.x;
                float pv[4];
                float r = 0.0f;
#pragma unroll
                for (int c = 0; c < 4; c++) {
                    float a = ap2[c];
                    float topo = (a == 0.0f) ? -1e9f : a;
                    float s = sp2[c] + topo + sbc * stqv[i] * stkv[c];
                    float p = fexp(s);
                    pv[c] = p;
                    r += p;
                }
                __nv_bfloat162 v01, v23;
                v01.x = __float2bfloat16(pv[0]); v01.y = __float2bfloat16(pv[1]);
                v23.x = __float2bfloat16(pv[2]); v23.y = __float2bfloat16(pv[3]);
                __nv_bfloat162* pd = (__nv_bfloat162*)&sP[row * LQ + fidx * 4];
                pd[0] = v01; pd[1] = v23;
                r += __shfl_xor_sync(0xffffffffu, r, 1);
                r += __shfl_xor_sync(0xffffffffu, r, 2);
                r += __shfl_xor_sync(0xffffffffu, r, 4);
                r += __shfl_xor_sync(0xffffffffu, r, 8);
                den[i] += r;
            }
        }

        // Store next K/V tile (regs -> other buffer)
        if (t < 63) {
            __nv_bfloat16* kd = sK + (b ^ 1) * BUF;
            __nv_bfloat16* vd = sV + (b ^ 1) * BUF;
            *(uint4*)&kd[d0] = kr0;            *(uint4*)&kd[d0 + 32 * LQ] = kr1;
            *(uint4*)&vd[d0] = vr0;            *(uint4*)&vd[d0 + 32 * LQ] = vr1;
            if (tid < 64) sStK[(b ^ 1) * 64 + tid] = stk;
        }
        // Prefetch K/V tile t+2 (regs)
        if (t < 62) {
            int off = (t + 2) * 512;
            kr0 = ks[off + tid]; kr1 = ks[off + tid + 256];
            vr0 = vs[off + tid]; vr1 = vs[off + tid + 256];
            if (tid < 64) stk = nf[(kvb + (t + 2) * 64 + tid) * 3 + 2];
        }
        // Prefetch adj tile t+1 (regs)
        if (t < 63) {
            const float* ap = adj + (size_t)q0 * NN + kvb + (t + 1) * 64;
            a0 = *(const float4*)&ap[(size_t)(rgrp)      * NN + fidx * 4];
            a1 = *(const float4*)&ap[(size_t)(rgrp + 16) * NN + fidx * 4];
            a2 = *(const float4*)&ap[(size_t)(rgrp + 32) * NN + fidx * 4];
            a3 = *(const float4*)&ap[(size_t)(rgrp + 48) * NN + fidx * 4];
        }
        __syncthreads();   // (B)

        // O += P @ V
#pragma unroll
        for (int kk = 0; kk < 4; kk++) {
            wmma::fragment<wmma::matrix_a, 16, 16, 16, __nv_bfloat16, wmma::row_major> fp;
            wmma::load_matrix_sync(fp, sP + wm_ * 16 * LQ + kk * 16, LQ);
            wmma::fragment<wmma::matrix_b, 16, 16, 16, __nv_bfloat16, wmma::row_major> fv0, fv1;
            wmma::load_matrix_sync(fv0, sVb + kk * 16 * LQ + wn_ * 32, LQ);
            wmma::load_matrix_sync(fv1, sVb + kk * 16 * LQ + wn_ * 32 + 16, LQ);
            wmma::mma_sync(o0, fp, fv0, o0);
            wmma::mma_sync(o1, fp, fv1, o1);
        }
    }

    // Write partial den
    if (fidx == 0) {
#pragma unroll
        for (int i = 0; i < 4; i++) g_denp[sp][q0 + rgrp + 16 * i] = den[i];
    }
    // Write partial numerator
    wmma::store_matrix_sync(sS + wm_ * 16 * LQ + wn_ * 32,      o0, LQ, wmma::mem_row_major);
    wmma::store_matrix_sync(sS + wm_ * 16 * LQ + wn_ * 32 + 16, o1, LQ, wmma::mem_row_major);
    __syncthreads();
#pragma unroll
    for (int k2 = 0; k2 < 16; k2++) {
        int idx = tid + k2 * 256;
        int row = idx >> 6;
        int col = idx & 63;
        g_aggp[sp][(q0 + row) * 64 + col] = sS[row * LQ + col];
    }
}

// ---------------------------------------------------------------------------
// K3: combine partials; z = h + num/den ; LayerNorm ; head MLP. 4 rows/warp.
__global__ __launch_bounds__(256) void k_epi(
    const float* __restrict__ sa, const float* __restrict__ lng, const float* __restrict__ lnb,
    const float* __restrict__ wa1, const float* __restrict__ ba1,
    const float* __restrict__ wa2, const float* __restrict__ ba2,
    float* __restrict__ out) {
    __shared__ float sAi[32][68];
    const int warp = threadIdx.x >> 5;
    const int lane = threadIdx.x & 31;
    const int base = blockIdx.x * 32 + warp * 4;
    const int c0 = lane, c1 = lane + 32;

#pragma unroll
    for (int r = 0; r < 4; r++) {
        int row = base + r;
        float invd = 1.0f / (g_denp[0][row] + g_denp[1][row]);
        float z0 = g_h[row * 64 + c0] + (g_aggp[0][row * 64 + c0] + g_aggp[1][row * 64 + c0]) * invd;
        float z1 = g_h[row * 64 + c1] + (g_aggp[0][row * 64 + c1] + g_aggp[1][row * 64 + c1]) * invd;
        float s = z0 + z1;
#pragma unroll
        for (int o = 16; o >= 1; o >>= 1) s += __shfl_xor_sync(0xffffffffu, s, o);
        float mu = s * (1.0f / 64.0f);
        float d0 = z0 - mu, d1 = z1 - mu;
        float v = d0 * d0 + d1 * d1;
#pragma unroll
        for (int o = 16; o >= 1; o >>= 1) v += __shfl_xor_sync(0xffffffffu, v, o);
        float inv = rsqrtf(v * (1.0f / 64.0f) + 1e-5f);
        sAi[warp * 4 + r][c0] = fmaf(d0 * inv, lng[c0], lnb[c0]);
        sAi[warp * 4 + r][c1] = fmaf(d1 * inv, lng[c1], lnb[c1]);
        if (lane < 2) sAi[warp * 4 + r][64 + lane] = sa[row * 2 + lane];
    }
    __syncwarp();

    float acc0[4], acc1[4];
    float bb0 = ba1[c0], bb1 = ba1[c1];
#pragma unroll
    for (int r = 0; r < 4; r++) { acc0[r] = bb0; acc1[r] = bb1; }
#pragma unroll 6
    for (int i = 0; i < 66; i++) {
        float w0 = wa1[i * 64 + c0];
        float w1v = wa1[i * 64 + c1];
#pragma unroll
        for (int r = 0; r < 4; r++) {
            acc0[r] = fmaf(sAi[warp * 4 + r][i], w0, acc0[r]);
            acc1[r] = fmaf(sAi[warp * 4 + r][i], w1v, acc1[r]);
        }
    }
    float w20 = wa2[c0 * 3 + 0], w21 = wa2[c0 * 3 + 1], w22 = wa2[c0 * 3 + 2];
    float w30 = wa2[c1 * 3 + 0], w31 = wa2[c1 * 3 + 1], w32 = wa2[c1 * 3 + 2];
#pragma unroll
    for (int r = 0; r < 4; r++) {
        float p0 = fmaxf(acc0[r], 0.0f);
        float p1 = fmaxf(acc1[r], 0.0f);
        float q0v = fmaf(p0, w20, p1 * w30);
        float q1v = fmaf(p0, w21, p1 * w31);
        float q2v = fmaf(p0, w22, p1 * w32);
#pragma unroll
        for (int o = 16; o >= 1; o >>= 1) {
            q0v += __shfl_xor_sync(0xffffffffu, q0v, o);
            q1v += __shfl_xor_sync(0xffffffffu, q1v, o);
            q2v += __shfl_xor_sync(0xffffffffu, q2v, o);
        }
        if (lane == 0) {
            int row = base + r;
            out[row * 3 + 0] = q0v + ba2[0];
            out[row * 3 + 1] = q1v + ba2[1];
            out[row * 3 + 2] = q2v + ba2[2];
        }
    }
}

// ---------------------------------------------------------------------------
extern "C" void kernel_launch(void* const* d_in, const int* in_sizes, int n_in,
                              void* d_out, int out_size) {
    const float* nf    = (const float*)d_in[0];
    const float* adj   = (const float*)d_in[1];
    const float* tc    = (const float*)d_in[2];
    const float* sa    = (const float*)d_in[3];
    const float* w1    = (const float*)d_in[4];
    const float* b1    = (const float*)d_in[5];
    const float* w2    = (const float*)d_in[6];
    const float* b2    = (const float*)d_in[7];
    const float* wq    = (const float*)d_in[8];
    const float* bq    = (const float*)d_in[9];
    const float* wk    = (const float*)d_in[10];
    const float* bk    = (const float*)d_in[11];
    const float* wg    = (const float*)d_in[12];
    const float* bg    = (const float*)d_in[13];
    const float* sbias = (const float*)d_in[14];
    const float* wm    = (const float*)d_in[15];
    const float* bm    = (const float*)d_in[16];
    const float* lng   = (const float*)d_in[17];
    const float* lnb   = (const float*)d_in[18];
    const float* wa1   = (const float*)d_in[19];
    const float* ba1   = (const float*)d_in[20];
    const float* wa2   = (const float*)d_in[21];
    const float* ba2   = (const float*)d_in[22];
    float* out = (float*)d_out;

    static bool attr_set = false;
    if (!attr_set) {
        cudaFuncSetAttribute(k_attn, cudaFuncAttributeMaxDynamicSharedMemorySize, SMEM_ATTN);
        attr_set = true;
    }

    k_scalars<<<1, 64>>>(tc, wg, bg, sbias);
    k_prep<<<128, 256>>>(nf, tc, w1, b1, w2, b2, wq, bq, wk, bk, wm, bm);
    k_attn<<<256, 256, SMEM_ATTN>>>(adj, nf);
    k_epi<<<256, 256>>>(sa, lng, lnb, wa1, ba1, wa2, ba2, out);
}